// round 11
// baseline (speedup 1.0000x reference)
#include <cuda_runtime.h>
#include <math_constants.h>
#include <cstdint>

#define BB    4
#define NN    2048
#define DIMC  768
#define HEADS 12
#define HD    64
#define MTOK  (BB * NN)   /* 8192 tokens */

// Scratch (allocation-free rule: __device__ globals)
__device__ float    g_qkv[(size_t)MTOK * 3 * DIMC];          // fp32 qkv
__device__ float    g_att[(size_t)MTOK * DIMC];              // fp32 attn out
__device__ uint32_t g_wt[(size_t)(3 * DIMC) * DIMC + (size_t)DIMC * DIMC]; // W^T tf32 (qkv | proj)
__device__ uint32_t g_qt[(size_t)MTOK * DIMC];               // Q  [bh][n][d'] tf32, prescaled
__device__ uint32_t g_kt[(size_t)MTOK * DIMC];               // K  [bh][n][d'] tf32
__device__ uint32_t g_vt[(size_t)MTOK * DIMC];               // V^T [bh][d][key'] tf32

// ---------------------------------------------------------------------------
// tf32 + mma helpers (sm_80+ PTX only)
// ---------------------------------------------------------------------------
__device__ __forceinline__ uint32_t f2tf(float x) {
    uint32_t r;
    asm("cvt.rna.tf32.f32 %0, %1;" : "=r"(r) : "f"(x));
    return r;
}

__device__ __forceinline__ void mma_tf32(float* d, const uint32_t* a, const uint32_t* b) {
    asm volatile(
        "mma.sync.aligned.m16n8k8.row.col.f32.tf32.tf32.f32 "
        "{%0,%1,%2,%3}, {%4,%5,%6,%7}, {%8,%9}, {%0,%1,%2,%3};"
        : "+f"(d[0]), "+f"(d[1]), "+f"(d[2]), "+f"(d[3])
        : "r"(a[0]), "r"(a[1]), "r"(a[2]), "r"(a[3]), "r"(b[0]), "r"(b[1]));
}

// Within-8 column permutation (R8-proven): logical j stored at
// p = (j&~7) + 2*(j&3) + (j>>2 & 1).  Inverse: j = (p&~7) + 4*(p&1) + ((p&7)>>1).
__device__ __forceinline__ int pcol(int c) {
    return (c & ~7) + ((c & 3) << 1) + ((c >> 2) & 1);
}
__device__ __forceinline__ int pinv(int p) {
    return (p & ~7) + ((p & 1) << 2) + ((p & 7) >> 1);
}

// ===========================================================================
// Weight transpose + tf32 convert + pcol permute:  W[768][Nc] -> WT[Nc][768]
// ===========================================================================
__global__ void transpose_w(const float* __restrict__ W, uint32_t* __restrict__ WT, int Nc)
{
    __shared__ float tile[32][33];
    const int kb = blockIdx.y * 32;   // k (768) block
    const int nb = blockIdx.x * 32;   // n block
    const int tx = threadIdx.x, ty = threadIdx.y;   // 32 x 8
#pragma unroll
    for (int i = 0; i < 32; i += 8)
        tile[ty + i][tx] = W[(size_t)(kb + ty + i) * Nc + nb + tx];
    __syncthreads();
    const int kp = pcol(tx);
#pragma unroll
    for (int i = 0; i < 32; i += 8)
        WT[(size_t)(nb + ty + i) * DIMC + kb + kp] = f2tf(tile[tx][ty + i]);
}

// ===========================================================================
// Prepass: qkv fp32 -> Q (prescaled) / K in [bh][n][64 d'] tf32 pcol layout
// grid = MTOK blocks, 192 threads (12 heads x 16 uint4-chunks)
// ===========================================================================
__global__ void prep_qk(const float* __restrict__ qkv,
                        uint32_t* __restrict__ Qt, uint32_t* __restrict__ Kt)
{
    const int tok = blockIdx.x;
    const int u   = threadIdx.x;          // 0..191
    const int h   = u >> 4, u64 = u & 15;
    const int v = u64 & 7, grp = u64 >> 3;
    const int b = tok >> 11, n = tok & 2047;

    const float* src = qkv + (size_t)tok * (3 * DIMC) + h * HD + grp * 32;
    uint32_t oq[4], ok[4];
#pragma unroll
    for (int j = 0; j < 4; j++) {
        const int p = v * 4 + j;          // storage position within 32
        const int k = pinv(p);            // logical d within 32
        oq[j] = f2tf(src[k] * 0.125f);
        ok[j] = f2tf(src[DIMC + k]);
    }
    const size_t orow = ((size_t)(b * HEADS + h) * NN + n) * HD + grp * 32 + v * 4;
    *(uint4*)&Qt[orow] = make_uint4(oq[0], oq[1], oq[2], oq[3]);
    *(uint4*)&Kt[orow] = make_uint4(ok[0], ok[1], ok[2], ok[3]);
}

// ===========================================================================
// Prepass: V -> V^T [bh][d][key'] tf32, keys pcol-permuted within 8-blocks
// grid = (keys/32, d/32=2, 48), block 32x8
// ===========================================================================
__global__ void prep_v(const float* __restrict__ qkv, uint32_t* __restrict__ Vt)
{
    __shared__ float tile[32][33];
    const int bh = blockIdx.z;
    const int b = bh / HEADS, h = bh % HEADS;
    const int keyb = blockIdx.x * 32, db = blockIdx.y * 32;
    const int tx = threadIdx.x, ty = threadIdx.y;
#pragma unroll
    for (int i = 0; i < 32; i += 8)
        tile[ty + i][tx] = qkv[(size_t)(b * NN + keyb + ty + i) * (3 * DIMC)
                               + 2 * DIMC + h * HD + db + tx];
    __syncthreads();
    const int kp = pcol(tx);
#pragma unroll
    for (int i = 0; i < 32; i += 8)
        Vt[((size_t)bh * HD + db + ty + i) * NN + keyb + kp] = f2tf(tile[tx][ty + i]);
}

// ===========================================================================
// GEMM: C[M,N] = A[M,K] @ W[K,N] + bias[N], BT = W^T tf32 pcol-permuted.
// 128x128 tile, BK=32, 8 warps (warp 32x64). Double-buffered smem.
// Fragment pattern identical to R8 (proven): uint2 at [row*GSTR + ks*8 + 2t].
// ===========================================================================
#define GSTR 36
#define GEMM_SMEM (18432 * 4)

__global__ __launch_bounds__(256, 1)
void gemm_mma(const float* __restrict__ A, const uint32_t* __restrict__ BT,
              const float* __restrict__ bias, float* __restrict__ C,
              int N, int K)
{
    extern __shared__ uint32_t dsm[];
    const int tid  = threadIdx.x;
    const int lane = tid & 31, wid = tid >> 5;
    const int g = lane >> 2, t = lane & 3;
    const int bm = blockIdx.y * 128, bn = blockIdx.x * 128;
    const int wm = (wid & 3) * 32, wn = (wid >> 2) * 64;

    const int ar = tid >> 1, ah = (tid & 1) * 16;
    const float*    Aq = A  + (size_t)(bm + ar) * K + ah;
    const uint32_t* Bq = BT + (size_t)(bn + ar) * K + ah;

    float acc[2][8][4];
#pragma unroll
    for (int mt = 0; mt < 2; mt++)
#pragma unroll
        for (int nt = 0; nt < 8; nt++)
#pragma unroll
            for (int r = 0; r < 4; r++) acc[mt][nt][r] = 0.0f;

    float4 a_ld[4];
    uint4  b_ld[4];

#define GEMM_LDG(kt) do {                                                    \
    _Pragma("unroll")                                                        \
    for (int i = 0; i < 4; i++) {                                            \
        a_ld[i] = *(const float4*)(Aq + (size_t)(kt) * 32 + 4 * i);          \
        b_ld[i] = *(const uint4*)(Bq + (size_t)(kt) * 32 + 4 * i);           \
    } } while (0)

#define GEMM_STS(buf) do {                                                   \
    uint32_t* as_ = dsm + (buf) * 9216;                                      \
    uint32_t* bs_ = as_ + 4608;                                              \
    _Pragma("unroll")                                                        \
    for (int i = 0; i < 4; i++) {                                            \
        const float av_[4] = {a_ld[i].x, a_ld[i].y, a_ld[i].z, a_ld[i].w};   \
        _Pragma("unroll")                                                    \
        for (int e = 0; e < 4; e++)                                          \
            as_[ar * GSTR + pcol(ah + i * 4 + e)] = f2tf(av_[e]);            \
        *(uint4*)&bs_[ar * GSTR + ah + 4 * i] = b_ld[i];                     \
    } } while (0)

    const int NT = K / 32;
    GEMM_LDG(0);
    GEMM_STS(0);

    for (int kt = 0; kt < NT; kt++) {
        __syncthreads();
        if (kt + 1 < NT) GEMM_LDG(kt + 1);

        const uint32_t* as = dsm + (kt & 1) * 9216;
        const uint32_t* bs = as + 4608;
#pragma unroll
        for (int ks = 0; ks < 4; ks++) {
            uint32_t af[2][4], bf[8][2];
#pragma unroll
            for (int mt = 0; mt < 2; mt++) {
                const int r0 = wm + mt * 16 + g;
                uint2 lo = *(const uint2*)&as[r0 * GSTR + ks * 8 + 2 * t];
                uint2 hi = *(const uint2*)&as[(r0 + 8) * GSTR + ks * 8 + 2 * t];
                af[mt][0] = lo.x; af[mt][1] = hi.x; af[mt][2] = lo.y; af[mt][3] = hi.y;
            }
#pragma unroll
            for (int nt = 0; nt < 8; nt++) {
                uint2 bb = *(const uint2*)&bs[(wn + nt * 8 + g) * GSTR + ks * 8 + 2 * t];
                bf[nt][0] = bb.x; bf[nt][1] = bb.y;
            }
#pragma unroll
            for (int mt = 0; mt < 2; mt++)
#pragma unroll
                for (int nt = 0; nt < 8; nt++)
                    mma_tf32(acc[mt][nt], af[mt], bf[nt]);
        }
        if (kt + 1 < NT) GEMM_STS((kt + 1) & 1);
    }

    // epilogue: bias + float2 stores
#pragma unroll
    for (int mt = 0; mt < 2; mt++)
#pragma unroll
        for (int rr = 0; rr < 2; rr++) {
            const int row = bm + wm + mt * 16 + g + rr * 8;
            float* Cr = C + (size_t)row * N;
#pragma unroll
            for (int nt = 0; nt < 8; nt++) {
                const int col = bn + wn + nt * 8 + 2 * t;
                float2 bb = *(const float2*)(bias + col);
                float2 o;
                o.x = acc[mt][nt][rr * 2 + 0] + bb.x;
                o.y = acc[mt][nt][rr * 2 + 1] + bb.y;
                *(float2*)(Cr + col) = o;
            }
        }
#undef GEMM_LDG
#undef GEMM_STS
}

// ===========================================================================
// Flash attention with prepacked tf32 Q/K/V^T (pcol layout). Block = (b,h,128 q).
// Fragment/softmax/P logic identical to R8 (proven). Stride 68.
// FIXED vs R9/R10: tile loaders now cover FULL tiles (Q: 2048 uint4,
// K/V: 1024 uint4 each — previously only 1/4 of each tile was loaded).
// smem words: Qs 8704 | Ks 4352 | Vs 4352 | Ps 8704 = 26112 (104448 B)
// ===========================================================================
#define AST 68
#define KS_OFF 8704
#define VS_OFF 13056
#define PS_OFF 17408
#define ATT_SMEM (26112 * 4)

__global__ __launch_bounds__(256, 2)
void attn_mma(const uint32_t* __restrict__ Qt, const uint32_t* __restrict__ Kt,
              const uint32_t* __restrict__ Vt, float* __restrict__ outp)
{
    extern __shared__ uint32_t dsm[];
    const int tid = threadIdx.x, lane = tid & 31, w = tid >> 5;
    const int g = lane >> 2, t = lane & 3;
    const int qt = blockIdx.x & 15;
    const int h  = (blockIdx.x >> 4) % HEADS;
    const int b  = blockIdx.x / (16 * HEADS);
    const int bh = b * HEADS + h;
    const int q0 = qt * 128;

    // ---- Q tile: 128 rows x 64 words = 2048 uint4; 8 per thread ----
    {
        const uint32_t* Qbase = Qt + ((size_t)bh * NN + q0) * HD;
#pragma unroll
        for (int i = 0; i < 8; i++) {
            const int idx = i * 256 + tid;
            const int row = idx >> 4, c = (idx & 15) * 4;
            uint4 v = *(const uint4*)&Qbase[(size_t)row * HD + c];
            *(uint4*)&dsm[row * AST + c] = v;
        }
    }

    float o[8][4];
#pragma unroll
    for (int nt = 0; nt < 8; nt++)
#pragma unroll
        for (int r = 0; r < 4; r++) o[nt][r] = 0.0f;
    float m0 = -CUDART_INF_F, m1 = -CUDART_INF_F, l0 = 0.0f, l1 = 0.0f;

    const int r0 = 16 * w + g;
    const uint32_t* Kbase = Kt + (size_t)bh * NN * HD;
    const uint32_t* Vbase = Vt + (size_t)bh * HD * NN;

    for (int kt = 0; kt < NN / 64; kt++) {
        // prefetch K tile (64x64) and V^T tile (64x64): 4 uint4 each per thread
        uint4 kf[4], vf[4];
#pragma unroll
        for (int i = 0; i < 4; i++) {
            const int idx = i * 256 + tid;
            const int row = idx >> 4, c = (idx & 15) * 4;
            kf[i] = *(const uint4*)&Kbase[((size_t)kt * 64 + row) * HD + c];
            vf[i] = *(const uint4*)&Vbase[(size_t)row * NN + kt * 64 + c];
        }
        __syncthreads();
#pragma unroll
        for (int i = 0; i < 4; i++) {
            const int idx = i * 256 + tid;
            const int row = idx >> 4, c = (idx & 15) * 4;
            *(uint4*)&dsm[KS_OFF + row * AST + c] = kf[i];
            *(uint4*)&dsm[VS_OFF + row * AST + c] = vf[i];
        }
        __syncthreads();

        // ---- S = Q @ K^T (R8 fragment pattern) ----
        float s[8][4];
#pragma unroll
        for (int nt = 0; nt < 8; nt++)
#pragma unroll
            for (int r = 0; r < 4; r++) s[nt][r] = 0.0f;

#pragma unroll
        for (int ks = 0; ks < 8; ks++) {
            uint2 alo = *(const uint2*)&dsm[r0 * AST + ks * 8 + 2 * t];
            uint2 ahi = *(const uint2*)&dsm[(r0 + 8) * AST + ks * 8 + 2 * t];
            uint32_t a[4] = {alo.x, ahi.x, alo.y, ahi.y};
#pragma unroll
            for (int nt = 0; nt < 8; nt++) {
                uint2 bb = *(const uint2*)&dsm[KS_OFF + (nt * 8 + g) * AST + ks * 8 + 2 * t];
                uint32_t bf2[2] = {bb.x, bb.y};
                mma_tf32(s[nt], a, bf2);
            }
        }

        // ---- online softmax (rows g and g+8; quad-local) ----
        float mx0 = -CUDART_INF_F, mx1 = -CUDART_INF_F;
#pragma unroll
        for (int nt = 0; nt < 8; nt++) {
            mx0 = fmaxf(mx0, fmaxf(s[nt][0], s[nt][1]));
            mx1 = fmaxf(mx1, fmaxf(s[nt][2], s[nt][3]));
        }
        mx0 = fmaxf(mx0, __shfl_xor_sync(0xffffffffu, mx0, 1));
        mx0 = fmaxf(mx0, __shfl_xor_sync(0xffffffffu, mx0, 2));
        mx1 = fmaxf(mx1, __shfl_xor_sync(0xffffffffu, mx1, 1));
        mx1 = fmaxf(mx1, __shfl_xor_sync(0xffffffffu, mx1, 2));
        const float nm0 = fmaxf(m0, mx0), nm1 = fmaxf(m1, mx1);
        const float cr0 = __expf(m0 - nm0), cr1 = __expf(m1 - nm1);
        float rs0 = 0.0f, rs1 = 0.0f;
#pragma unroll
        for (int nt = 0; nt < 8; nt++) {
            s[nt][0] = __expf(s[nt][0] - nm0);
            s[nt][1] = __expf(s[nt][1] - nm0);
            s[nt][2] = __expf(s[nt][2] - nm1);
            s[nt][3] = __expf(s[nt][3] - nm1);
            rs0 += s[nt][0] + s[nt][1];
            rs1 += s[nt][2] + s[nt][3];
        }
        rs0 += __shfl_xor_sync(0xffffffffu, rs0, 1);
        rs0 += __shfl_xor_sync(0xffffffffu, rs0, 2);
        rs1 += __shfl_xor_sync(0xffffffffu, rs1, 1);
        rs1 += __shfl_xor_sync(0xffffffffu, rs1, 2);
        l0 = l0 * cr0 + rs0;  m0 = nm0;
        l1 = l1 * cr1 + rs1;  m1 = nm1;
#pragma unroll
        for (int nt = 0; nt < 8; nt++) {
            o[nt][0] *= cr0; o[nt][1] *= cr0;
            o[nt][2] *= cr1; o[nt][3] *= cr1;
        }

        // ---- P: C-frag -> smem, pcol layout (warp-private rows; R8 verbatim) ----
#pragma unroll
        for (int nt = 0; nt < 8; nt++) {
            const int j0 = nt * 8 + 2 * t;
            dsm[PS_OFF + r0 * AST + pcol(j0)]           = f2tf(s[nt][0]);
            dsm[PS_OFF + r0 * AST + pcol(j0 + 1)]       = f2tf(s[nt][1]);
            dsm[PS_OFF + (r0 + 8) * AST + pcol(j0)]     = f2tf(s[nt][2]);
            dsm[PS_OFF + (r0 + 8) * AST + pcol(j0 + 1)] = f2tf(s[nt][3]);
        }
        __syncwarp();

        // ---- O += P @ V (R8 fragment pattern) ----
#pragma unroll
        for (int ks = 0; ks < 8; ks++) {
            uint2 plo = *(const uint2*)&dsm[PS_OFF + r0 * AST + ks * 8 + 2 * t];
            uint2 phi = *(const uint2*)&dsm[PS_OFF + (r0 + 8) * AST + ks * 8 + 2 * t];
            uint32_t a[4] = {plo.x, phi.x, plo.y, phi.y};
#pragma unroll
            for (int nt = 0; nt < 8; nt++) {
                uint2 bb = *(const uint2*)&dsm[VS_OFF + (nt * 8 + g) * AST + ks * 8 + 2 * t];
                uint32_t bf2[2] = {bb.x, bb.y};
                mma_tf32(o[nt], a, bf2);
            }
        }
        __syncwarp();
    }

    // ---- epilogue: normalize, store to [B*N, 768] ----
    const float inv0 = 1.0f / l0, inv1 = 1.0f / l1;
    const int grow = b * NN + q0 + 16 * w + g;
    float* or0 = outp + (size_t)grow * DIMC + h * HD;
    float* or1 = outp + (size_t)(grow + 8) * DIMC + h * HD;
#pragma unroll
    for (int nt = 0; nt < 8; nt++) {
        const int col = nt * 8 + 2 * t;
        float2 v0; v0.x = o[nt][0] * inv0; v0.y = o[nt][1] * inv0;
        float2 v1; v1.x = o[nt][2] * inv1; v1.y = o[nt][3] * inv1;
        *(float2*)(or0 + col) = v0;
        *(float2*)(or1 + col) = v1;
    }
}

// ---------------------------------------------------------------------------
extern "C" void kernel_launch(void* const* d_in, const int* in_sizes, int n_in,
                              void* d_out, int out_size)
{
    const float* x      = (const float*)d_in[0];
    const float* w_qkv  = (const float*)d_in[1];
    const float* b_qkv  = (const float*)d_in[2];
    const float* w_proj = (const float*)d_in[3];
    const float* b_proj = (const float*)d_in[4];
    float* out = (float*)d_out;

    float *qkv_s = nullptr, *att_s = nullptr;
    uint32_t *wt_s = nullptr, *qt_s = nullptr, *kt_s = nullptr, *vt_s = nullptr;
    cudaGetSymbolAddress((void**)&qkv_s, g_qkv);
    cudaGetSymbolAddress((void**)&att_s, g_att);
    cudaGetSymbolAddress((void**)&wt_s,  g_wt);
    cudaGetSymbolAddress((void**)&qt_s,  g_qt);
    cudaGetSymbolAddress((void**)&kt_s,  g_kt);
    cudaGetSymbolAddress((void**)&vt_s,  g_vt);

    cudaFuncSetAttribute(gemm_mma, cudaFuncAttributeMaxDynamicSharedMemorySize, GEMM_SMEM);
    cudaFuncSetAttribute(attn_mma, cudaFuncAttributeMaxDynamicSharedMemorySize, ATT_SMEM);

    uint32_t* wqkvT = wt_s;
    uint32_t* wprjT = wt_s + (size_t)(3 * DIMC) * DIMC;

    // 0) weight transposes (tf32 + pcol permute)
    transpose_w<<<dim3((3 * DIMC) / 32, DIMC / 32), dim3(32, 8)>>>(w_qkv, wqkvT, 3 * DIMC);
    transpose_w<<<dim3(DIMC / 32, DIMC / 32), dim3(32, 8)>>>(w_proj, wprjT, DIMC);

    // 1) QKV GEMM: [8192,768] @ [768,2304] + bias
    gemm_mma<<<dim3((3 * DIMC) / 128, MTOK / 128), 256, GEMM_SMEM>>>(
        x, wqkvT, b_qkv, qkv_s, 3 * DIMC, DIMC);

    // 2) prepass: Q/K pcol tf32, V transposed pcol tf32
    prep_qk<<<MTOK, 192>>>(qkv_s, qt_s, kt_s);
    prep_v<<<dim3(NN / 32, HD / 32, BB * HEADS), dim3(32, 8)>>>(qkv_s, vt_s);

    // 3) flash attention
    attn_mma<<<BB * HEADS * 16, 256, ATT_SMEM>>>(qt_s, kt_s, vt_s, att_s);

    // 4) projection GEMM: [8192,768] @ [768,768] + bias
    gemm_mma<<<dim3(DIMC / 128, MTOK / 128), 256, GEMM_SMEM>>>(
        att_s, wprjT, b_proj, out, DIMC, DIMC);
}

// round 12
// speedup vs baseline: 2.0995x; 2.0995x over previous
#include <cuda_runtime.h>
#include <cuda_fp16.h>
#include <math_constants.h>
#include <cstdint>

#define BB    4
#define NN    2048
#define DIMC  768
#define HEADS 12
#define HD    64
#define MTOK  (BB * NN)   /* 8192 tokens */

// Scratch (allocation-free rule: __device__ globals)
__device__ float    g_qkv[(size_t)MTOK * 3 * DIMC];          // fp32 qkv
__device__ float    g_att[(size_t)MTOK * DIMC];              // fp32 attn out
__device__ uint32_t g_wt[(size_t)(3 * DIMC) * (DIMC / 2) + (size_t)DIMC * (DIMC / 2)]; // W^T fp16x2
__device__ uint32_t g_qt[(size_t)MTOK * (DIMC / 2)];         // Q  [bh][n][32w] fp16x2, prescaled
__device__ uint32_t g_kt[(size_t)MTOK * (DIMC / 2)];         // K  [bh][n][32w] fp16x2
__device__ uint32_t g_vt[(size_t)MTOK * (DIMC / 2)];         // V^T [bh][d][1024w] fp16x2

// ---------------------------------------------------------------------------
// fp16 helpers (sm_80+ PTX only)
// ---------------------------------------------------------------------------
__device__ __forceinline__ uint32_t packh2(float a, float b) {
    __half2 h = __floats2half2_rn(a, b);   // low = a (even k), high = b (odd k)
    return *reinterpret_cast<uint32_t*>(&h);
}

// D += A @ B ; m16n8k16 fp16 inputs, fp32 accumulate.
// A frag (4xb32): a0=(g, k2t:2t+1) a1=(g+8, same) a2=(g, k2t+8:+9) a3=(g+8, same)
// B frag (2xb32): b0=(k2t:2t+1, n=g) b1=(k2t+8:+9, n=g)
// C frag: c0=(g,2t) c1=(g,2t+1) c2=(g+8,2t) c3=(g+8,2t+1)
__device__ __forceinline__ void mma_f16(float* d, const uint32_t* a, const uint32_t* b) {
    asm volatile(
        "mma.sync.aligned.m16n8k16.row.col.f32.f16.f16.f32 "
        "{%0,%1,%2,%3}, {%4,%5,%6,%7}, {%8,%9}, {%0,%1,%2,%3};"
        : "+f"(d[0]), "+f"(d[1]), "+f"(d[2]), "+f"(d[3])
        : "r"(a[0]), "r"(a[1]), "r"(a[2]), "r"(a[3]), "r"(b[0]), "r"(b[1]));
}

// Word permutation within an 8-word (16-k) block: word w (k pair 2w,2w+1)
// stored at p8(w) = 2*(w&3) + (w>>2); inverse w = 4*(p&1) + (p>>1).
// uint2 load at +2t then yields words {t, t+4} = k pairs (2t,2t+1),(2t+8,2t+9).
__device__ __forceinline__ int p8(int w)   { return ((w & 3) << 1) + (w >> 2); }
__device__ __forceinline__ int p8inv(int p){ return ((p & 1) << 2) + (p >> 1); }

// ===========================================================================
// Weight transpose + fp16 pack + word-permute:  W[768][Nc] -> WT[Nc][384w]
// block (16,16); grid (Nc/32, 768/32)
// ===========================================================================
__global__ void transpose_w(const float* __restrict__ W, uint32_t* __restrict__ WT, int Nc)
{
    __shared__ float tile[32][33];
    const int kb = blockIdx.y * 32;   // k block
    const int nb = blockIdx.x * 32;   // n block
    const int tx = threadIdx.x, ty = threadIdx.y;
    const int tid = ty * 16 + tx;
#pragma unroll
    for (int i = 0; i < 4; i++) {
        const int idx = i * 256 + tid;
        const int k = idx >> 5, n = idx & 31;
        tile[k][n] = W[(size_t)(kb + k) * Nc + nb + n];
    }
    __syncthreads();
    const int blk = tx >> 3, wi = tx & 7;
    const int pos = blk * 8 + p8(wi);       // permuted word pos within 16
#pragma unroll
    for (int i = 0; i < 2; i++) {
        const int n = ty + i * 16;
        WT[(size_t)(nb + n) * (DIMC / 2) + (kb >> 1) + pos] =
            packh2(tile[2 * tx][n], tile[2 * tx + 1][n]);
    }
}

// ===========================================================================
// Prepass: qkv fp32 -> Q (prescaled) / K as [bh][n][32w] fp16x2, word-permuted
// grid = MTOK, 192 threads (12 heads x 16 uint2-chunks)
// ===========================================================================
__global__ void prep_qk(const float* __restrict__ qkv,
                        uint32_t* __restrict__ Qt, uint32_t* __restrict__ Kt)
{
    const int tok = blockIdx.x;
    const int u   = threadIdx.x;          // 0..191
    const int h   = u >> 4, pw = (u & 15) * 2;   // output word positions pw, pw+1
    const int b = tok >> 11, n = tok & 2047;

    const float* src = qkv + (size_t)tok * (3 * DIMC) + h * HD;
    uint32_t oq[2], ok[2];
#pragma unroll
    for (int j = 0; j < 2; j++) {
        const int p = pw + j;
        const int w = (p & ~7) + p8inv(p & 7);   // logical word
        const int d0 = 2 * w;
        oq[j] = packh2(src[d0] * 0.125f, src[d0 + 1] * 0.125f);
        ok[j] = packh2(src[DIMC + d0], src[DIMC + d0 + 1]);
    }
    const size_t orow = ((size_t)(b * HEADS + h) * NN + n) * (HD / 2) + pw;
    *(uint2*)&Qt[orow] = make_uint2(oq[0], oq[1]);
    *(uint2*)&Kt[orow] = make_uint2(ok[0], ok[1]);
}

// ===========================================================================
// Prepass: V -> V^T [bh][d][1024w] fp16x2, key-pairs word-permuted
// block (16,16); grid (NN/32, HD/32, 48)
// ===========================================================================
__global__ void prep_v(const float* __restrict__ qkv, uint32_t* __restrict__ Vt)
{
    __shared__ float tile[32][33];   // [key][d]
    const int bh = blockIdx.z;
    const int b = bh / HEADS, h = bh % HEADS;
    const int keyb = blockIdx.x * 32, db = blockIdx.y * 32;
    const int tx = threadIdx.x, ty = threadIdx.y;
    const int tid = ty * 16 + tx;
#pragma unroll
    for (int i = 0; i < 4; i++) {
        const int idx = i * 256 + tid;
        const int key = idx >> 5, d = idx & 31;
        tile[key][d] = qkv[(size_t)(b * NN + keyb + key) * (3 * DIMC)
                           + 2 * DIMC + h * HD + db + d];
    }
    __syncthreads();
    const int blk = tx >> 3, wi = tx & 7;
    const int pos = blk * 8 + p8(wi);
#pragma unroll
    for (int i = 0; i < 2; i++) {
        const int d = ty + i * 16;
        Vt[((size_t)bh * HD + db + d) * (NN / 2) + (keyb >> 1) + pos] =
            packh2(tile[2 * tx][d], tile[2 * tx + 1][d]);
    }
}

// ===========================================================================
// GEMM: C[M,N] = A[M,K] @ W[K,N] + bias[N], BT = W^T fp16x2 word-permuted.
// 128x128 tile, BK=32 (2 k16 blocks), 8 warps (warp 32x64). Double-buffered.
// smem row = 16 words + 8 pad = 24 (conflict-free fragment loads).
// ===========================================================================
#define GSTR 24
#define GEMM_SMEM (12288 * 4)   /* 2 * (128*24 + 128*24) words */

__global__ __launch_bounds__(256, 1)
void gemm_mma(const float* __restrict__ A, const uint32_t* __restrict__ BT,
              const float* __restrict__ bias, float* __restrict__ C,
              int N, int K)
{
    extern __shared__ uint32_t dsm[];
    const int tid  = threadIdx.x;
    const int lane = tid & 31, wid = tid >> 5;
    const int g = lane >> 2, t = lane & 3;
    const int bm = blockIdx.y * 128, bn = blockIdx.x * 128;
    const int wm = (wid & 3) * 32, wn = (wid >> 2) * 64;

    const int ar  = tid >> 1;            // row 0..127 (shared by A and B tiles)
    const int ablk = tid & 1;            // k16 block 0/1 (A), word-half 0/1 (B)
    const float*    Aq = A  + (size_t)(bm + ar) * K + ablk * 16;
    const uint32_t* Bq = BT + (size_t)(bn + ar) * (K / 2) + ablk * 8;

    float acc[2][8][4];
#pragma unroll
    for (int mt = 0; mt < 2; mt++)
#pragma unroll
        for (int nt = 0; nt < 8; nt++)
#pragma unroll
            for (int r = 0; r < 4; r++) acc[mt][nt][r] = 0.0f;

    float4 a_ld[4];
    uint4  b_ld[2];

#define GEMM_LDG(kt) do {                                                    \
    _Pragma("unroll")                                                        \
    for (int i = 0; i < 4; i++)                                              \
        a_ld[i] = *(const float4*)(Aq + (size_t)(kt) * 32 + 4 * i);          \
    b_ld[0] = *(const uint4*)(Bq + (size_t)(kt) * 16);                       \
    b_ld[1] = *(const uint4*)(Bq + (size_t)(kt) * 16 + 4);                   \
    } while (0)

#define GEMM_STS(buf) do {                                                   \
    uint32_t* as_ = dsm + (buf) * 6144;                                      \
    uint32_t* bs_ = as_ + 3072;                                              \
    const float f_[16] = {a_ld[0].x, a_ld[0].y, a_ld[0].z, a_ld[0].w,        \
                          a_ld[1].x, a_ld[1].y, a_ld[1].z, a_ld[1].w,        \
                          a_ld[2].x, a_ld[2].y, a_ld[2].z, a_ld[2].w,        \
                          a_ld[3].x, a_ld[3].y, a_ld[3].z, a_ld[3].w};       \
    _Pragma("unroll")                                                        \
    for (int w_ = 0; w_ < 8; w_++)                                           \
        as_[ar * GSTR + ablk * 8 + p8(w_)] = packh2(f_[2 * w_], f_[2 * w_ + 1]); \
    *(uint4*)&bs_[ar * GSTR + ablk * 8]     = b_ld[0];                       \
    *(uint4*)&bs_[ar * GSTR + ablk * 8 + 4] = b_ld[1];                       \
    } while (0)

    const int NT = K / 32;
    GEMM_LDG(0);
    GEMM_STS(0);

    for (int kt = 0; kt < NT; kt++) {
        __syncthreads();
        if (kt + 1 < NT) GEMM_LDG(kt + 1);

        const uint32_t* as = dsm + (kt & 1) * 6144;
        const uint32_t* bs = as + 3072;
#pragma unroll
        for (int kb = 0; kb < 2; kb++) {
            uint32_t af[2][4], bf[8][2];
#pragma unroll
            for (int mt = 0; mt < 2; mt++) {
                const int r0 = wm + mt * 16 + g;
                uint2 lo = *(const uint2*)&as[r0 * GSTR + kb * 8 + 2 * t];
                uint2 hi = *(const uint2*)&as[(r0 + 8) * GSTR + kb * 8 + 2 * t];
                af[mt][0] = lo.x; af[mt][1] = hi.x; af[mt][2] = lo.y; af[mt][3] = hi.y;
            }
#pragma unroll
            for (int nt = 0; nt < 8; nt++) {
                uint2 bb = *(const uint2*)&bs[(wn + nt * 8 + g) * GSTR + kb * 8 + 2 * t];
                bf[nt][0] = bb.x; bf[nt][1] = bb.y;
            }
#pragma unroll
            for (int mt = 0; mt < 2; mt++)
#pragma unroll
                for (int nt = 0; nt < 8; nt++)
                    mma_f16(acc[mt][nt], af[mt], bf[nt]);
        }
        if (kt + 1 < NT) GEMM_STS((kt + 1) & 1);
    }

    // epilogue: bias + float2 stores
#pragma unroll
    for (int mt = 0; mt < 2; mt++)
#pragma unroll
        for (int rr = 0; rr < 2; rr++) {
            const int row = bm + wm + mt * 16 + g + rr * 8;
            float* Cr = C + (size_t)row * N;
#pragma unroll
            for (int nt = 0; nt < 8; nt++) {
                const int col = bn + wn + nt * 8 + 2 * t;
                float2 bb = *(const float2*)(bias + col);
                float2 o;
                o.x = acc[mt][nt][rr * 2 + 0] + bb.x;
                o.y = acc[mt][nt][rr * 2 + 1] + bb.y;
                *(float2*)(Cr + col) = o;
            }
        }
#undef GEMM_LDG
#undef GEMM_STS
}

// ===========================================================================
// Flash attention, fp16 m16n8k16, prepacked Q/K/V^T. Block = (b,h,128 q).
// smem words (stride 40): Qs 5120 | Ks 2560 | Vs 2560 | Ps 5120 = 15360 (61440 B)
// ===========================================================================
#define AST 40
#define KS_OFF 5120
#define VS_OFF 7680
#define PS_OFF 10240
#define ATT_SMEM (15360 * 4)

__global__ __launch_bounds__(256, 2)
void attn_mma(const uint32_t* __restrict__ Qt, const uint32_t* __restrict__ Kt,
              const uint32_t* __restrict__ Vt, float* __restrict__ outp)
{
    extern __shared__ uint32_t dsm[];
    const int tid = threadIdx.x, lane = tid & 31, w = tid >> 5;
    const int g = lane >> 2, t = lane & 3;
    const int qt = blockIdx.x & 15;
    const int h  = (blockIdx.x >> 4) % HEADS;
    const int b  = blockIdx.x / (16 * HEADS);
    const int bh = b * HEADS + h;
    const int q0 = qt * 128;

    // ---- Q tile: 128 rows x 32 words = 1024 uint4; 4 per thread ----
    {
        const uint32_t* Qbase = Qt + ((size_t)bh * NN + q0) * (HD / 2);
#pragma unroll
        for (int i = 0; i < 4; i++) {
            const int idx = i * 256 + tid;
            const int row = idx >> 3, c = (idx & 7) * 4;
            uint4 v = *(const uint4*)&Qbase[(size_t)row * (HD / 2) + c];
            *(uint4*)&dsm[row * AST + c] = v;
        }
    }

    float o[8][4];
#pragma unroll
    for (int nt = 0; nt < 8; nt++)
#pragma unroll
        for (int r = 0; r < 4; r++) o[nt][r] = 0.0f;
    float m0 = -CUDART_INF_F, m1 = -CUDART_INF_F, l0 = 0.0f, l1 = 0.0f;

    const int r0 = 16 * w + g;
    const uint32_t* Kbase = Kt + (size_t)bh * NN * (HD / 2);
    const uint32_t* Vbase = Vt + (size_t)bh * HD * (NN / 2);

    for (int kt = 0; kt < NN / 64; kt++) {
        // prefetch K tile (64 keys x 32w) and V^T tile (64 d x 32w): 2 uint4 each
        uint4 kf[2], vf[2];
#pragma unroll
        for (int i = 0; i < 2; i++) {
            const int idx = i * 256 + tid;
            const int row = idx >> 3, c = (idx & 7) * 4;
            kf[i] = *(const uint4*)&Kbase[((size_t)kt * 64 + row) * (HD / 2) + c];
            vf[i] = *(const uint4*)&Vbase[(size_t)row * (NN / 2) + kt * 32 + c];
        }
        __syncthreads();
#pragma unroll
        for (int i = 0; i < 2; i++) {
            const int idx = i * 256 + tid;
            const int row = idx >> 3, c = (idx & 7) * 4;
            *(uint4*)&dsm[KS_OFF + row * AST + c] = kf[i];
            *(uint4*)&dsm[VS_OFF + row * AST + c] = vf[i];
        }
        __syncthreads();

        // ---- S = Q @ K^T : 4 k16 blocks over d=64 ----
        float s[8][4];
#pragma unroll
        for (int nt = 0; nt < 8; nt++)
#pragma unroll
            for (int r = 0; r < 4; r++) s[nt][r] = 0.0f;

#pragma unroll
        for (int kb = 0; kb < 4; kb++) {
            uint2 alo = *(const uint2*)&dsm[r0 * AST + kb * 8 + 2 * t];
            uint2 ahi = *(const uint2*)&dsm[(r0 + 8) * AST + kb * 8 + 2 * t];
            uint32_t a[4] = {alo.x, ahi.x, alo.y, ahi.y};
#pragma unroll
            for (int nt = 0; nt < 8; nt++) {
                uint2 bb = *(const uint2*)&dsm[KS_OFF + (nt * 8 + g) * AST + kb * 8 + 2 * t];
                uint32_t bf2[2] = {bb.x, bb.y};
                mma_f16(s[nt], a, bf2);
            }
        }

        // ---- online softmax (rows g and g+8; quad-local) ----
        float mx0 = -CUDART_INF_F, mx1 = -CUDART_INF_F;
#pragma unroll
        for (int nt = 0; nt < 8; nt++) {
            mx0 = fmaxf(mx0, fmaxf(s[nt][0], s[nt][1]));
            mx1 = fmaxf(mx1, fmaxf(s[nt][2], s[nt][3]));
        }
        mx0 = fmaxf(mx0, __shfl_xor_sync(0xffffffffu, mx0, 1));
        mx0 = fmaxf(mx0, __shfl_xor_sync(0xffffffffu, mx0, 2));
        mx1 = fmaxf(mx1, __shfl_xor_sync(0xffffffffu, mx1, 1));
        mx1 = fmaxf(mx1, __shfl_xor_sync(0xffffffffu, mx1, 2));
        const float nm0 = fmaxf(m0, mx0), nm1 = fmaxf(m1, mx1);
        const float cr0 = __expf(m0 - nm0), cr1 = __expf(m1 - nm1);
        float rs0 = 0.0f, rs1 = 0.0f;
#pragma unroll
        for (int nt = 0; nt < 8; nt++) {
            s[nt][0] = __expf(s[nt][0] - nm0);
            s[nt][1] = __expf(s[nt][1] - nm0);
            s[nt][2] = __expf(s[nt][2] - nm1);
            s[nt][3] = __expf(s[nt][3] - nm1);
            rs0 += s[nt][0] + s[nt][1];
            rs1 += s[nt][2] + s[nt][3];
        }
        rs0 += __shfl_xor_sync(0xffffffffu, rs0, 1);
        rs0 += __shfl_xor_sync(0xffffffffu, rs0, 2);
        rs1 += __shfl_xor_sync(0xffffffffu, rs1, 1);
        rs1 += __shfl_xor_sync(0xffffffffu, rs1, 2);
        l0 = l0 * cr0 + rs0;  m0 = nm0;
        l1 = l1 * cr1 + rs1;  m1 = nm1;
#pragma unroll
        for (int nt = 0; nt < 8; nt++) {
            o[nt][0] *= cr0; o[nt][1] *= cr0;
            o[nt][2] *= cr1; o[nt][3] *= cr1;
        }

        // ---- P: C-frag -> smem fp16x2, word-permuted (warp-private rows) ----
        // word w = nt*4+t covers keys (8nt+2t, +1); pos = (nt>>1)*8 + 2t + (nt&1)
#pragma unroll
        for (int nt = 0; nt < 8; nt++) {
            const int pos = (nt >> 1) * 8 + 2 * t + (nt & 1);
            dsm[PS_OFF + r0 * AST + pos]       = packh2(s[nt][0], s[nt][1]);
            dsm[PS_OFF + (r0 + 8) * AST + pos] = packh2(s[nt][2], s[nt][3]);
        }
        __syncwarp();

        // ---- O += P @ V : 4 k16 blocks over 64 keys ----
#pragma unroll
        for (int kb = 0; kb < 4; kb++) {
            uint2 plo = *(const uint2*)&dsm[PS_OFF + r0 * AST + kb * 8 + 2 * t];
            uint2 phi = *(const uint2*)&dsm[PS_OFF + (r0 + 8) * AST + kb * 8 + 2 * t];
            uint32_t a[4] = {plo.x, phi.x, plo.y, phi.y};
#pragma unroll
            for (int nt = 0; nt < 8; nt++) {
                uint2 bb = *(const uint2*)&dsm[VS_OFF + (nt * 8 + g) * AST + kb * 8 + 2 * t];
                uint32_t bf2[2] = {bb.x, bb.y};
                mma_f16(o[nt], a, bf2);
            }
        }
        __syncwarp();
    }

    // ---- epilogue: normalize, store to [B*N, 768] ----
    const float inv0 = 1.0f / l0, inv1 = 1.0f / l1;
    const int grow = b * NN + q0 + 16 * w + g;
    float* or0 = outp + (size_t)grow * DIMC + h * HD;
    float* or1 = outp + (size_t)(grow + 8) * DIMC + h * HD;
#pragma unroll
    for (int nt = 0; nt < 8; nt++) {
        const int col = nt * 8 + 2 * t;
        float2 v0; v0.x = o[nt][0] * inv0; v0.y = o[nt][1] * inv0;
        float2 v1; v1.x = o[nt][2] * inv1; v1.y = o[nt][3] * inv1;
        *(float2*)(or0 + col) = v0;
        *(float2*)(or1 + col) = v1;
    }
}

// ---------------------------------------------------------------------------
extern "C" void kernel_launch(void* const* d_in, const int* in_sizes, int n_in,
                              void* d_out, int out_size)
{
    const float* x      = (const float*)d_in[0];
    const float* w_qkv  = (const float*)d_in[1];
    const float* b_qkv  = (const float*)d_in[2];
    const float* w_proj = (const float*)d_in[3];
    const float* b_proj = (const float*)d_in[4];
    float* out = (float*)d_out;

    float *qkv_s = nullptr, *att_s = nullptr;
    uint32_t *wt_s = nullptr, *qt_s = nullptr, *kt_s = nullptr, *vt_s = nullptr;
    cudaGetSymbolAddress((void**)&qkv_s, g_qkv);
    cudaGetSymbolAddress((void**)&att_s, g_att);
    cudaGetSymbolAddress((void**)&wt_s,  g_wt);
    cudaGetSymbolAddress((void**)&qt_s,  g_qt);
    cudaGetSymbolAddress((void**)&kt_s,  g_kt);
    cudaGetSymbolAddress((void**)&vt_s,  g_vt);

    cudaFuncSetAttribute(gemm_mma, cudaFuncAttributeMaxDynamicSharedMemorySize, GEMM_SMEM);
    cudaFuncSetAttribute(attn_mma, cudaFuncAttributeMaxDynamicSharedMemorySize, ATT_SMEM);

    uint32_t* wqkvT = wt_s;
    uint32_t* wprjT = wt_s + (size_t)(3 * DIMC) * (DIMC / 2);

    // 0) weight transposes (fp16 pack + word permute)
    transpose_w<<<dim3((3 * DIMC) / 32, DIMC / 32), dim3(16, 16)>>>(w_qkv, wqkvT, 3 * DIMC);
    transpose_w<<<dim3(DIMC / 32, DIMC / 32), dim3(16, 16)>>>(w_proj, wprjT, DIMC);

    // 1) QKV GEMM: [8192,768] @ [768,2304] + bias
    gemm_mma<<<dim3((3 * DIMC) / 128, MTOK / 128), 256, GEMM_SMEM>>>(
        x, wqkvT, b_qkv, qkv_s, 3 * DIMC, DIMC);

    // 2) prepass: Q/K fp16 packed, V transposed fp16 packed
    prep_qk<<<MTOK, 192>>>(qkv_s, qt_s, kt_s);
    prep_v<<<dim3(NN / 32, HD / 32, BB * HEADS), dim3(16, 16)>>>(qkv_s, vt_s);

    // 3) flash attention
    attn_mma<<<BB * HEADS * 16, 256, ATT_SMEM>>>(qt_s, kt_s, vt_s, att_s);

    // 4) projection GEMM: [8192,768] @ [768,768] + bias
    gemm_mma<<<dim3(DIMC / 128, MTOK / 128), 256, GEMM_SMEM>>>(
        att_s, wprjT, b_proj, out, DIMC, DIMC);
}

// round 13
// speedup vs baseline: 2.5555x; 1.2172x over previous
#include <cuda_runtime.h>
#include <cuda_fp16.h>
#include <math_constants.h>
#include <cstdint>

#define BB    4
#define NN    2048
#define DIMC  768
#define HEADS 12
#define HD    64
#define MTOK  (BB * NN)   /* 8192 tokens */

// Scratch (allocation-free rule: __device__ globals)
__device__ float    g_qkv[(size_t)MTOK * 3 * DIMC];          // fp32 qkv (V region used)
__device__ float    g_att[(size_t)MTOK * DIMC];              // fp32 attn out
__device__ uint32_t g_wt[(size_t)(3 * DIMC) * (DIMC / 2) + (size_t)DIMC * (DIMC / 2)]; // W^T fp16x2
__device__ uint32_t g_qt[(size_t)MTOK * (DIMC / 2)];         // Q  [bh][n][32w] fp16x2, prescaled
__device__ uint32_t g_kt[(size_t)MTOK * (DIMC / 2)];         // K  [bh][n][32w] fp16x2
__device__ uint32_t g_vt[(size_t)MTOK * (DIMC / 2)];         // V^T [bh][d][1024w] fp16x2

// ---------------------------------------------------------------------------
// fp16 helpers (sm_80+ PTX only)
// ---------------------------------------------------------------------------
__device__ __forceinline__ uint32_t packh2(float a, float b) {
    __half2 h = __floats2half2_rn(a, b);   // low = a (even k), high = b (odd k)
    return *reinterpret_cast<uint32_t*>(&h);
}

__device__ __forceinline__ void mma_f16(float* d, const uint32_t* a, const uint32_t* b) {
    asm volatile(
        "mma.sync.aligned.m16n8k16.row.col.f32.f16.f16.f32 "
        "{%0,%1,%2,%3}, {%4,%5,%6,%7}, {%8,%9}, {%0,%1,%2,%3};"
        : "+f"(d[0]), "+f"(d[1]), "+f"(d[2]), "+f"(d[3])
        : "r"(a[0]), "r"(a[1]), "r"(a[2]), "r"(a[3]), "r"(b[0]), "r"(b[1]));
}

// Word permutation within an 8-word (16-k) block: word w (k pair 2w,2w+1)
// stored at p8(w) = 2*(w&3) + (w>>2); inverse w = 4*(p&1) + (p>>1).
__device__ __forceinline__ int p8(int w)   { return ((w & 3) << 1) + (w >> 2); }
__device__ __forceinline__ int p8inv(int p){ return ((p & 1) << 2) + (p >> 1); }

// ===========================================================================
// Weight transpose + fp16 pack + word-permute:  W[768][Nc] -> WT[Nc][384w]
// ===========================================================================
__global__ void transpose_w(const float* __restrict__ W, uint32_t* __restrict__ WT, int Nc)
{
    __shared__ float tile[32][33];
    const int kb = blockIdx.y * 32;
    const int nb = blockIdx.x * 32;
    const int tx = threadIdx.x, ty = threadIdx.y;
    const int tid = ty * 16 + tx;
#pragma unroll
    for (int i = 0; i < 4; i++) {
        const int idx = i * 256 + tid;
        const int k = idx >> 5, n = idx & 31;
        tile[k][n] = W[(size_t)(kb + k) * Nc + nb + n];
    }
    __syncthreads();
    const int blk = tx >> 3, wi = tx & 7;
    const int pos = blk * 8 + p8(wi);
#pragma unroll
    for (int i = 0; i < 2; i++) {
        const int n = ty + i * 16;
        WT[(size_t)(nb + n) * (DIMC / 2) + (kb >> 1) + pos] =
            packh2(tile[2 * tx][n], tile[2 * tx + 1][n]);
    }
}

// ===========================================================================
// Prepass: V -> V^T [bh][d][1024w] fp16x2, key-pairs word-permuted
// ===========================================================================
__global__ void prep_v(const float* __restrict__ qkv, uint32_t* __restrict__ Vt)
{
    __shared__ float tile[32][33];   // [key][d]
    const int bh = blockIdx.z;
    const int b = bh / HEADS, h = bh % HEADS;
    const int keyb = blockIdx.x * 32, db = blockIdx.y * 32;
    const int tx = threadIdx.x, ty = threadIdx.y;
    const int tid = ty * 16 + tx;
#pragma unroll
    for (int i = 0; i < 4; i++) {
        const int idx = i * 256 + tid;
        const int key = idx >> 5, d = idx & 31;
        tile[key][d] = qkv[(size_t)(b * NN + keyb + key) * (3 * DIMC)
                           + 2 * DIMC + h * HD + db + d];
    }
    __syncthreads();
    const int blk = tx >> 3, wi = tx & 7;
    const int pos = blk * 8 + p8(wi);
#pragma unroll
    for (int i = 0; i < 2; i++) {
        const int d = ty + i * 16;
        Vt[((size_t)bh * HD + db + d) * (NN / 2) + (keyb >> 1) + pos] =
            packh2(tile[2 * tx][d], tile[2 * tx + 1][d]);
    }
}

// ===========================================================================
// GEMM: C[M,N] = A[M,K] @ W[K,N] + bias[N], BT = W^T fp16x2 word-permuted.
// 128x128 tile, BK=32 (2 k16 blocks), 8 warps (warp 32x64). Double-buffered.
// fused!=0 (QKV GEMM): Q/K columns (col<1536) are written packed-fp16 straight
// into Qt/Kt prepacked layouts (Q prescaled by 0.125); V columns go fp32 to C.
// ===========================================================================
#define GSTR 24
#define GEMM_SMEM (12288 * 4)

__global__ __launch_bounds__(256, 2)
void gemm_mma(const float* __restrict__ A, const uint32_t* __restrict__ BT,
              const float* __restrict__ bias, float* __restrict__ C,
              uint32_t* __restrict__ Qt, uint32_t* __restrict__ Kt,
              int N, int K, int fused)
{
    extern __shared__ uint32_t dsm[];
    const int tid  = threadIdx.x;
    const int lane = tid & 31, wid = tid >> 5;
    const int g = lane >> 2, t = lane & 3;
    const int bm = blockIdx.y * 128, bn = blockIdx.x * 128;
    const int wm = (wid & 3) * 32, wn = (wid >> 2) * 64;

    const int ar  = tid >> 1;
    const int ablk = tid & 1;
    const float*    Aq = A  + (size_t)(bm + ar) * K + ablk * 16;
    const uint32_t* Bq = BT + (size_t)(bn + ar) * (K / 2) + ablk * 8;

    float acc[2][8][4];
#pragma unroll
    for (int mt = 0; mt < 2; mt++)
#pragma unroll
        for (int nt = 0; nt < 8; nt++)
#pragma unroll
            for (int r = 0; r < 4; r++) acc[mt][nt][r] = 0.0f;

    float4 a_ld[4];
    uint4  b_ld[2];

#define GEMM_LDG(kt) do {                                                    \
    _Pragma("unroll")                                                        \
    for (int i = 0; i < 4; i++)                                              \
        a_ld[i] = *(const float4*)(Aq + (size_t)(kt) * 32 + 4 * i);          \
    b_ld[0] = *(const uint4*)(Bq + (size_t)(kt) * 16);                       \
    b_ld[1] = *(const uint4*)(Bq + (size_t)(kt) * 16 + 4);                   \
    } while (0)

#define GEMM_STS(buf) do {                                                   \
    uint32_t* as_ = dsm + (buf) * 6144;                                      \
    uint32_t* bs_ = as_ + 3072;                                              \
    const float f_[16] = {a_ld[0].x, a_ld[0].y, a_ld[0].z, a_ld[0].w,        \
                          a_ld[1].x, a_ld[1].y, a_ld[1].z, a_ld[1].w,        \
                          a_ld[2].x, a_ld[2].y, a_ld[2].z, a_ld[2].w,        \
                          a_ld[3].x, a_ld[3].y, a_ld[3].z, a_ld[3].w};       \
    _Pragma("unroll")                                                        \
    for (int w_ = 0; w_ < 8; w_++)                                           \
        as_[ar * GSTR + ablk * 8 + p8(w_)] = packh2(f_[2 * w_], f_[2 * w_ + 1]); \
    *(uint4*)&bs_[ar * GSTR + ablk * 8]     = b_ld[0];                       \
    *(uint4*)&bs_[ar * GSTR + ablk * 8 + 4] = b_ld[1];                       \
    } while (0)

    const int NT = K / 32;
    GEMM_LDG(0);
    GEMM_STS(0);

    for (int kt = 0; kt < NT; kt++) {
        __syncthreads();
        if (kt + 1 < NT) GEMM_LDG(kt + 1);

        const uint32_t* as = dsm + (kt & 1) * 6144;
        const uint32_t* bs = as + 3072;
#pragma unroll
        for (int kb = 0; kb < 2; kb++) {
            uint32_t af[2][4], bf[8][2];
#pragma unroll
            for (int mt = 0; mt < 2; mt++) {
                const int r0 = wm + mt * 16 + g;
                uint2 lo = *(const uint2*)&as[r0 * GSTR + kb * 8 + 2 * t];
                uint2 hi = *(const uint2*)&as[(r0 + 8) * GSTR + kb * 8 + 2 * t];
                af[mt][0] = lo.x; af[mt][1] = hi.x; af[mt][2] = lo.y; af[mt][3] = hi.y;
            }
#pragma unroll
            for (int nt = 0; nt < 8; nt++) {
                uint2 bb = *(const uint2*)&bs[(wn + nt * 8 + g) * GSTR + kb * 8 + 2 * t];
                bf[nt][0] = bb.x; bf[nt][1] = bb.y;
            }
#pragma unroll
            for (int mt = 0; mt < 2; mt++)
#pragma unroll
                for (int nt = 0; nt < 8; nt++)
                    mma_f16(acc[mt][nt], af[mt], bf[nt]);
        }
        if (kt + 1 < NT) GEMM_STS((kt + 1) & 1);
    }

    // epilogue
    const bool pack_qk = (fused != 0) && (bn + wn < 1536);   // uniform per warp
#pragma unroll
    for (int mt = 0; mt < 2; mt++)
#pragma unroll
        for (int rr = 0; rr < 2; rr++) {
            const int row = bm + wm + mt * 16 + g + rr * 8;
            float* Cr = C + (size_t)row * N;
            const int btok = row >> 11, ntok = row & 2047;
#pragma unroll
            for (int nt = 0; nt < 8; nt++) {
                const int col = bn + wn + nt * 8 + 2 * t;
                float2 bb = *(const float2*)(bias + col);
                const float v0 = acc[mt][nt][rr * 2 + 0] + bb.x;
                const float v1 = acc[mt][nt][rr * 2 + 1] + bb.y;
                if (pack_qk) {
                    const bool isQ = col < 768;
                    const int within = isQ ? col : (col - 768);
                    const int h = within >> 6, d = within & 63;
                    const int w = d >> 1;
                    const int pos = (w & ~7) + p8(w & 7);
                    const uint32_t word = isQ ? packh2(v0 * 0.125f, v1 * 0.125f)
                                              : packh2(v0, v1);
                    uint32_t* dst = isQ ? Qt : Kt;
                    dst[((size_t)(btok * HEADS + h) * NN + ntok) * (HD / 2) + pos] = word;
                } else {
                    float2 o; o.x = v0; o.y = v1;
                    *(float2*)(Cr + col) = o;
                }
            }
        }
#undef GEMM_LDG
#undef GEMM_STS
}

// ===========================================================================
// Flash attention, fp16 m16n8k16. Q fragments live in REGISTERS (loaded once
// from prepacked global). K/V software-pipelined: LDG(kt+1) overlaps compute.
// smem words (stride 40): Ks 2560 | Vs 2560 | Ps 5120 = 10240 (40960 B)
// ===========================================================================
#define AST 40
#define KS_OFF 0
#define VS_OFF 2560
#define PS_OFF 5120
#define ATT_SMEM (10240 * 4)

__global__ __launch_bounds__(256, 2)
void attn_mma(const uint32_t* __restrict__ Qt, const uint32_t* __restrict__ Kt,
              const uint32_t* __restrict__ Vt, float* __restrict__ outp)
{
    extern __shared__ uint32_t dsm[];
    const int tid = threadIdx.x, lane = tid & 31, w = tid >> 5;
    const int g = lane >> 2, t = lane & 3;
    const int qt = blockIdx.x & 15;
    const int h  = (blockIdx.x >> 4) % HEADS;
    const int b  = blockIdx.x / (16 * HEADS);
    const int bh = b * HEADS + h;
    const int q0 = qt * 128;
    const int r0 = 16 * w + g;

    // ---- Q fragments straight from global into registers (one time) ----
    uint32_t qa[4][4];
    {
        const uint32_t* Qr0 = Qt + ((size_t)bh * NN + q0 + r0) * (HD / 2);
        const uint32_t* Qr8 = Qr0 + 8 * (HD / 2);
#pragma unroll
        for (int kb = 0; kb < 4; kb++) {
            uint2 lo = *(const uint2*)&Qr0[kb * 8 + 2 * t];
            uint2 hi = *(const uint2*)&Qr8[kb * 8 + 2 * t];
            qa[kb][0] = lo.x; qa[kb][1] = hi.x; qa[kb][2] = lo.y; qa[kb][3] = hi.y;
        }
    }

    float o[8][4];
#pragma unroll
    for (int nt = 0; nt < 8; nt++)
#pragma unroll
        for (int r = 0; r < 4; r++) o[nt][r] = 0.0f;
    float m0 = -CUDART_INF_F, m1 = -CUDART_INF_F, l0 = 0.0f, l1 = 0.0f;

    const uint32_t* Kbase = Kt + (size_t)bh * NN * (HD / 2);
    const uint32_t* Vbase = Vt + (size_t)bh * HD * (NN / 2);

    const int ld_row = tid >> 3, ld_c = (tid & 7) * 4;      // chunk 0 of 2
    const int ld_row2 = 32 + ld_row;                        // chunk 1

    uint4 kf[2], vf[2];
#define ATT_LDG(kt) do {                                                      \
    kf[0] = *(const uint4*)&Kbase[((size_t)(kt) * 64 + ld_row)  * (HD / 2) + ld_c]; \
    kf[1] = *(const uint4*)&Kbase[((size_t)(kt) * 64 + ld_row2) * (HD / 2) + ld_c]; \
    vf[0] = *(const uint4*)&Vbase[(size_t)ld_row  * (NN / 2) + (kt) * 32 + ld_c];   \
    vf[1] = *(const uint4*)&Vbase[(size_t)ld_row2 * (NN / 2) + (kt) * 32 + ld_c];   \
    } while (0)

    ATT_LDG(0);

    for (int kt = 0; kt < NN / 64; kt++) {
        __syncthreads();   // previous iter's Ks/Vs reads complete
        *(uint4*)&dsm[KS_OFF + ld_row  * AST + ld_c] = kf[0];
        *(uint4*)&dsm[KS_OFF + ld_row2 * AST + ld_c] = kf[1];
        *(uint4*)&dsm[VS_OFF + ld_row  * AST + ld_c] = vf[0];
        *(uint4*)&dsm[VS_OFF + ld_row2 * AST + ld_c] = vf[1];
        __syncthreads();
        if (kt + 1 < NN / 64) ATT_LDG(kt + 1);   // overlaps compute below

        // ---- S = Q @ K^T : 4 k16 blocks over d=64, Q from registers ----
        float s[8][4];
#pragma unroll
        for (int nt = 0; nt < 8; nt++)
#pragma unroll
            for (int r = 0; r < 4; r++) s[nt][r] = 0.0f;

#pragma unroll
        for (int kb = 0; kb < 4; kb++) {
#pragma unroll
            for (int nt = 0; nt < 8; nt++) {
                uint2 bb = *(const uint2*)&dsm[KS_OFF + (nt * 8 + g) * AST + kb * 8 + 2 * t];
                uint32_t bf2[2] = {bb.x, bb.y};
                mma_f16(s[nt], qa[kb], bf2);
            }
        }

        // ---- online softmax (rows g and g+8; quad-local) ----
        float mx0 = -CUDART_INF_F, mx1 = -CUDART_INF_F;
#pragma unroll
        for (int nt = 0; nt < 8; nt++) {
            mx0 = fmaxf(mx0, fmaxf(s[nt][0], s[nt][1]));
            mx1 = fmaxf(mx1, fmaxf(s[nt][2], s[nt][3]));
        }
        mx0 = fmaxf(mx0, __shfl_xor_sync(0xffffffffu, mx0, 1));
        mx0 = fmaxf(mx0, __shfl_xor_sync(0xffffffffu, mx0, 2));
        mx1 = fmaxf(mx1, __shfl_xor_sync(0xffffffffu, mx1, 1));
        mx1 = fmaxf(mx1, __shfl_xor_sync(0xffffffffu, mx1, 2));
        const float nm0 = fmaxf(m0, mx0), nm1 = fmaxf(m1, mx1);
        const float cr0 = __expf(m0 - nm0), cr1 = __expf(m1 - nm1);
        float rs0 = 0.0f, rs1 = 0.0f;
#pragma unroll
        for (int nt = 0; nt < 8; nt++) {
            s[nt][0] = __expf(s[nt][0] - nm0);
            s[nt][1] = __expf(s[nt][1] - nm0);
            s[nt][2] = __expf(s[nt][2] - nm1);
            s[nt][3] = __expf(s[nt][3] - nm1);
            rs0 += s[nt][0] + s[nt][1];
            rs1 += s[nt][2] + s[nt][3];
        }
        rs0 += __shfl_xor_sync(0xffffffffu, rs0, 1);
        rs0 += __shfl_xor_sync(0xffffffffu, rs0, 2);
        rs1 += __shfl_xor_sync(0xffffffffu, rs1, 1);
        rs1 += __shfl_xor_sync(0xffffffffu, rs1, 2);
        l0 = l0 * cr0 + rs0;  m0 = nm0;
        l1 = l1 * cr1 + rs1;  m1 = nm1;
#pragma unroll
        for (int nt = 0; nt < 8; nt++) {
            o[nt][0] *= cr0; o[nt][1] *= cr0;
            o[nt][2] *= cr1; o[nt][3] *= cr1;
        }

        // ---- P: C-frag -> smem fp16x2, word-permuted (warp-private rows) ----
#pragma unroll
        for (int nt = 0; nt < 8; nt++) {
            const int pos = (nt >> 1) * 8 + 2 * t + (nt & 1);
            dsm[PS_OFF + r0 * AST + pos]       = packh2(s[nt][0], s[nt][1]);
            dsm[PS_OFF + (r0 + 8) * AST + pos] = packh2(s[nt][2], s[nt][3]);
        }
        __syncwarp();

        // ---- O += P @ V : 4 k16 blocks over 64 keys ----
#pragma unroll
        for (int kb = 0; kb < 4; kb++) {
            uint2 plo = *(const uint2*)&dsm[PS_OFF + r0 * AST + kb * 8 + 2 * t];
            uint2 phi = *(const uint2*)&dsm[PS_OFF + (r0 + 8) * AST + kb * 8 + 2 * t];
            uint32_t a[4] = {plo.x, phi.x, plo.y, phi.y};
#pragma unroll
            for (int nt = 0; nt < 8; nt++) {
                uint2 bb = *(const uint2*)&dsm[VS_OFF + (nt * 8 + g) * AST + kb * 8 + 2 * t];
                uint32_t bf2[2] = {bb.x, bb.y};
                mma_f16(o[nt], a, bf2);
            }
        }
    }

    // ---- epilogue: normalize, store to [B*N, 768] ----
    const float inv0 = 1.0f / l0, inv1 = 1.0f / l1;
    const int grow = b * NN + q0 + 16 * w + g;
    float* or0 = outp + (size_t)grow * DIMC + h * HD;
    float* or1 = outp + (size_t)(grow + 8) * DIMC + h * HD;
#pragma unroll
    for (int nt = 0; nt < 8; nt++) {
        const int col = nt * 8 + 2 * t;
        float2 v0; v0.x = o[nt][0] * inv0; v0.y = o[nt][1] * inv0;
        float2 v1; v1.x = o[nt][2] * inv1; v1.y = o[nt][3] * inv1;
        *(float2*)(or0 + col) = v0;
        *(float2*)(or1 + col) = v1;
    }
#undef ATT_LDG
}

// ---------------------------------------------------------------------------
extern "C" void kernel_launch(void* const* d_in, const int* in_sizes, int n_in,
                              void* d_out, int out_size)
{
    const float* x      = (const float*)d_in[0];
    const float* w_qkv  = (const float*)d_in[1];
    const float* b_qkv  = (const float*)d_in[2];
    const float* w_proj = (const float*)d_in[3];
    const float* b_proj = (const float*)d_in[4];
    float* out = (float*)d_out;

    float *qkv_s = nullptr, *att_s = nullptr;
    uint32_t *wt_s = nullptr, *qt_s = nullptr, *kt_s = nullptr, *vt_s = nullptr;
    cudaGetSymbolAddress((void**)&qkv_s, g_qkv);
    cudaGetSymbolAddress((void**)&att_s, g_att);
    cudaGetSymbolAddress((void**)&wt_s,  g_wt);
    cudaGetSymbolAddress((void**)&qt_s,  g_qt);
    cudaGetSymbolAddress((void**)&kt_s,  g_kt);
    cudaGetSymbolAddress((void**)&vt_s,  g_vt);

    cudaFuncSetAttribute(gemm_mma, cudaFuncAttributeMaxDynamicSharedMemorySize, GEMM_SMEM);
    cudaFuncSetAttribute(attn_mma, cudaFuncAttributeMaxDynamicSharedMemorySize, ATT_SMEM);

    uint32_t* wqkvT = wt_s;
    uint32_t* wprjT = wt_s + (size_t)(3 * DIMC) * (DIMC / 2);

    // 0) weight transposes (fp16 pack + word permute)
    transpose_w<<<dim3((3 * DIMC) / 32, DIMC / 32), dim3(16, 16)>>>(w_qkv, wqkvT, 3 * DIMC);
    transpose_w<<<dim3(DIMC / 32, DIMC / 32), dim3(16, 16)>>>(w_proj, wprjT, DIMC);

    // 1) QKV GEMM with fused Q/K packing (V written fp32 to g_qkv)
    gemm_mma<<<dim3((3 * DIMC) / 128, MTOK / 128), 256, GEMM_SMEM>>>(
        x, wqkvT, b_qkv, qkv_s, qt_s, kt_s, 3 * DIMC, DIMC, 1);

    // 2) prepass: V transposed fp16 packed
    prep_v<<<dim3(NN / 32, HD / 32, BB * HEADS), dim3(16, 16)>>>(qkv_s, vt_s);

    // 3) flash attention
    attn_mma<<<BB * HEADS * 16, 256, ATT_SMEM>>>(qt_s, kt_s, vt_s, att_s);

    // 4) projection GEMM: [8192,768] @ [768,768] + bias
    gemm_mma<<<dim3(DIMC / 128, MTOK / 128), 256, GEMM_SMEM>>>(
        att_s, wprjT, b_proj, out, nullptr, nullptr, DIMC, DIMC, 0);
}

// round 14
// speedup vs baseline: 2.7694x; 1.0837x over previous
#include <cuda_runtime.h>
#include <cuda_fp16.h>
#include <math_constants.h>
#include <cstdint>

#define BB    4
#define NN    2048
#define DIMC  768
#define HEADS 12
#define HD    64
#define MTOK  (BB * NN)   /* 8192 tokens */

// Scratch (allocation-free rule: __device__ globals)
__device__ float    g_qkv[(size_t)MTOK * 3 * DIMC];          // fp32 qkv (V region used)
__device__ uint32_t g_x16[(size_t)MTOK * (DIMC / 2)];        // x packed fp16, A-layout
__device__ uint32_t g_att16[(size_t)MTOK * (DIMC / 2)];      // attn out packed fp16, A-layout
__device__ uint32_t g_wt[(size_t)(3 * DIMC) * (DIMC / 2) + (size_t)DIMC * (DIMC / 2)]; // W^T fp16x2
__device__ uint32_t g_qt[(size_t)MTOK * (DIMC / 2)];         // Q  [bh][n][32w] fp16x2, prescaled
__device__ uint32_t g_kt[(size_t)MTOK * (DIMC / 2)];         // K  [bh][n][32w] fp16x2
__device__ uint32_t g_vt[(size_t)MTOK * (DIMC / 2)];         // V^T [bh][d][1024w] fp16x2

// ---------------------------------------------------------------------------
// fp16 helpers (sm_80+ PTX only)
// ---------------------------------------------------------------------------
__device__ __forceinline__ uint32_t packh2(float a, float b) {
    __half2 h = __floats2half2_rn(a, b);   // low = a (even k), high = b (odd k)
    return *reinterpret_cast<uint32_t*>(&h);
}

__device__ __forceinline__ void mma_f16(float* d, const uint32_t* a, const uint32_t* b) {
    asm volatile(
        "mma.sync.aligned.m16n8k16.row.col.f32.f16.f16.f32 "
        "{%0,%1,%2,%3}, {%4,%5,%6,%7}, {%8,%9}, {%0,%1,%2,%3};"
        : "+f"(d[0]), "+f"(d[1]), "+f"(d[2]), "+f"(d[3])
        : "r"(a[0]), "r"(a[1]), "r"(a[2]), "r"(a[3]), "r"(b[0]), "r"(b[1]));
}

// Word permutation within an 8-word (16-k) block: word w (k pair 2w,2w+1)
// stored at p8(w) = 2*(w&3) + (w>>2); inverse w = 4*(p&1) + (p>>1).
__device__ __forceinline__ int p8(int w)   { return ((w & 3) << 1) + (w >> 2); }
__device__ __forceinline__ int p8inv(int p){ return ((p & 1) << 2) + (p >> 1); }

// ===========================================================================
// Weight transpose + fp16 pack + word-permute:  W[768][Nc] -> WT[Nc][384w]
// ===========================================================================
__global__ void transpose_w(const float* __restrict__ W, uint32_t* __restrict__ WT, int Nc)
{
    __shared__ float tile[32][33];
    const int kb = blockIdx.y * 32;
    const int nb = blockIdx.x * 32;
    const int tx = threadIdx.x, ty = threadIdx.y;
    const int tid = ty * 16 + tx;
#pragma unroll
    for (int i = 0; i < 4; i++) {
        const int idx = i * 256 + tid;
        const int k = idx >> 5, n = idx & 31;
        tile[k][n] = W[(size_t)(kb + k) * Nc + nb + n];
    }
    __syncthreads();
    const int blk = tx >> 3, wi = tx & 7;
    const int pos = blk * 8 + p8(wi);
#pragma unroll
    for (int i = 0; i < 2; i++) {
        const int n = ty + i * 16;
        WT[(size_t)(nb + n) * (DIMC / 2) + (kb >> 1) + pos] =
            packh2(tile[2 * tx][n], tile[2 * tx + 1][n]);
    }
}

// ===========================================================================
// Prepass: x fp32 [8192][768] -> packed fp16 A-layout [8192][384w] (permuted)
// grid = MTOK*384/(4*256) = 3072, block 256; 4 words (1 uint4) per thread
// ===========================================================================
__global__ void prep_x(const float* __restrict__ x, uint32_t* __restrict__ X16)
{
    const int idx4 = blockIdx.x * 256 + threadIdx.x;
    const size_t base = (size_t)idx4 * 4;
    const int row = (int)(base / (DIMC / 2));
    const int p0  = (int)(base % (DIMC / 2));
    const float* src = x + (size_t)row * DIMC;
    uint32_t o[4];
#pragma unroll
    for (int j = 0; j < 4; j++) {
        const int p = p0 + j;
        const int w = (p & ~7) + p8inv(p & 7);
        o[j] = packh2(src[2 * w], src[2 * w + 1]);
    }
    *(uint4*)&X16[base] = make_uint4(o[0], o[1], o[2], o[3]);
}

// ===========================================================================
// Prepass: V -> V^T [bh][d][1024w] fp16x2, key-pairs word-permuted
// ===========================================================================
__global__ void prep_v(const float* __restrict__ qkv, uint32_t* __restrict__ Vt)
{
    __shared__ float tile[32][33];   // [key][d]
    const int bh = blockIdx.z;
    const int b = bh / HEADS, h = bh % HEADS;
    const int keyb = blockIdx.x * 32, db = blockIdx.y * 32;
    const int tx = threadIdx.x, ty = threadIdx.y;
    const int tid = ty * 16 + tx;
#pragma unroll
    for (int i = 0; i < 4; i++) {
        const int idx = i * 256 + tid;
        const int key = idx >> 5, d = idx & 31;
        tile[key][d] = qkv[(size_t)(b * NN + keyb + key) * (3 * DIMC)
                           + 2 * DIMC + h * HD + db + d];
    }
    __syncthreads();
    const int blk = tx >> 3, wi = tx & 7;
    const int pos = blk * 8 + p8(wi);
#pragma unroll
    for (int i = 0; i < 2; i++) {
        const int d = ty + i * 16;
        Vt[((size_t)bh * HD + db + d) * (NN / 2) + (keyb >> 1) + pos] =
            packh2(tile[2 * tx][d], tile[2 * tx + 1][d]);
    }
}

// ===========================================================================
// GEMM: C[M,N] = A[M,K] @ W[K,N] + bias[N].
// BOTH operands prepacked fp16x2 word-permuted -> pure LDG.128/STS.128 fills.
// 128x128 tile, BK=32, 8 warps (warp 32x64). Double-buffered smem.
// fused!=0 (QKV): Q/K cols (<1536) written packed to Qt/Kt; V cols fp32 to C.
// ===========================================================================
#define GSTR 24
#define GEMM_SMEM (12288 * 4)

__global__ __launch_bounds__(256, 2)
void gemm_mma(const uint32_t* __restrict__ A16, const uint32_t* __restrict__ BT,
              const float* __restrict__ bias, float* __restrict__ C,
              uint32_t* __restrict__ Qt, uint32_t* __restrict__ Kt,
              int N, int K, int fused)
{
    extern __shared__ uint32_t dsm[];
    const int tid  = threadIdx.x;
    const int lane = tid & 31, wid = tid >> 5;
    const int g = lane >> 2, t = lane & 3;
    const int bm = blockIdx.y * 128, bn = blockIdx.x * 128;
    const int wm = (wid & 3) * 32, wn = (wid >> 2) * 64;

    const int ar  = tid >> 1;
    const int ablk = tid & 1;
    const uint32_t* Aq = A16 + (size_t)(bm + ar) * (K / 2) + ablk * 8;
    const uint32_t* Bq = BT  + (size_t)(bn + ar) * (K / 2) + ablk * 8;

    float acc[2][8][4];
#pragma unroll
    for (int mt = 0; mt < 2; mt++)
#pragma unroll
        for (int nt = 0; nt < 8; nt++)
#pragma unroll
            for (int r = 0; r < 4; r++) acc[mt][nt][r] = 0.0f;

    uint4 a_ld[2], b_ld[2];

#define GEMM_LDG(kt) do {                                                    \
    a_ld[0] = *(const uint4*)(Aq + (size_t)(kt) * 16);                       \
    a_ld[1] = *(const uint4*)(Aq + (size_t)(kt) * 16 + 4);                   \
    b_ld[0] = *(const uint4*)(Bq + (size_t)(kt) * 16);                       \
    b_ld[1] = *(const uint4*)(Bq + (size_t)(kt) * 16 + 4);                   \
    } while (0)

#define GEMM_STS(buf) do {                                                   \
    uint32_t* as_ = dsm + (buf) * 6144;                                      \
    uint32_t* bs_ = as_ + 3072;                                              \
    *(uint4*)&as_[ar * GSTR + ablk * 8]     = a_ld[0];                       \
    *(uint4*)&as_[ar * GSTR + ablk * 8 + 4] = a_ld[1];                       \
    *(uint4*)&bs_[ar * GSTR + ablk * 8]     = b_ld[0];                       \
    *(uint4*)&bs_[ar * GSTR + ablk * 8 + 4] = b_ld[1];                       \
    } while (0)

    const int NT = K / 32;
    GEMM_LDG(0);
    GEMM_STS(0);

    for (int kt = 0; kt < NT; kt++) {
        __syncthreads();
        if (kt + 1 < NT) GEMM_LDG(kt + 1);

        const uint32_t* as = dsm + (kt & 1) * 6144;
        const uint32_t* bs = as + 3072;
#pragma unroll
        for (int kb = 0; kb < 2; kb++) {
            uint32_t af[2][4], bf[8][2];
#pragma unroll
            for (int mt = 0; mt < 2; mt++) {
                const int r0 = wm + mt * 16 + g;
                uint2 lo = *(const uint2*)&as[r0 * GSTR + kb * 8 + 2 * t];
                uint2 hi = *(const uint2*)&as[(r0 + 8) * GSTR + kb * 8 + 2 * t];
                af[mt][0] = lo.x; af[mt][1] = hi.x; af[mt][2] = lo.y; af[mt][3] = hi.y;
            }
#pragma unroll
            for (int nt = 0; nt < 8; nt++) {
                uint2 bb = *(const uint2*)&bs[(wn + nt * 8 + g) * GSTR + kb * 8 + 2 * t];
                bf[nt][0] = bb.x; bf[nt][1] = bb.y;
            }
#pragma unroll
            for (int mt = 0; mt < 2; mt++)
#pragma unroll
                for (int nt = 0; nt < 8; nt++)
                    mma_f16(acc[mt][nt], af[mt], bf[nt]);
        }
        if (kt + 1 < NT) GEMM_STS((kt + 1) & 1);
    }

    // epilogue
    const bool pack_qk = (fused != 0) && (bn + wn < 1536);   // uniform per warp
#pragma unroll
    for (int mt = 0; mt < 2; mt++)
#pragma unroll
        for (int rr = 0; rr < 2; rr++) {
            const int row = bm + wm + mt * 16 + g + rr * 8;
            float* Cr = C + (size_t)row * N;
            const int btok = row >> 11, ntok = row & 2047;
#pragma unroll
            for (int nt = 0; nt < 8; nt++) {
                const int col = bn + wn + nt * 8 + 2 * t;
                float2 bb = *(const float2*)(bias + col);
                const float v0 = acc[mt][nt][rr * 2 + 0] + bb.x;
                const float v1 = acc[mt][nt][rr * 2 + 1] + bb.y;
                if (pack_qk) {
                    const bool isQ = col < 768;
                    const int within = isQ ? col : (col - 768);
                    const int h = within >> 6, d = within & 63;
                    const int w = d >> 1;
                    const int pos = (w & ~7) + p8(w & 7);
                    const uint32_t word = isQ ? packh2(v0 * 0.125f, v1 * 0.125f)
                                              : packh2(v0, v1);
                    uint32_t* dst = isQ ? Qt : Kt;
                    dst[((size_t)(btok * HEADS + h) * NN + ntok) * (HD / 2) + pos] = word;
                } else {
                    float2 o; o.x = v0; o.y = v1;
                    *(float2*)(Cr + col) = o;
                }
            }
        }
#undef GEMM_LDG
#undef GEMM_STS
}

// ===========================================================================
// Flash attention, fp16 m16n8k16. Q fragments in registers; P fragments built
// by register packing (C-frag IS A-frag-shaped for fp16) — no P smem at all.
// K/V double-buffered: ONE __syncthreads per k-tile.
// smem words: 2 bufs x (Ks 2560 | Vs 2560) = 10240 (40960 B)
// Output written packed fp16 in GEMM-A layout (g_att16).
// ===========================================================================
#define AST 40
#define ATT_SMEM (10240 * 4)

__global__ __launch_bounds__(256, 2)
void attn_mma(const uint32_t* __restrict__ Qt, const uint32_t* __restrict__ Kt,
              const uint32_t* __restrict__ Vt, uint32_t* __restrict__ att16)
{
    extern __shared__ uint32_t dsm[];
    const int tid = threadIdx.x, lane = tid & 31, w = tid >> 5;
    const int g = lane >> 2, t = lane & 3;
    const int qt = blockIdx.x & 15;
    const int h  = (blockIdx.x >> 4) % HEADS;
    const int b  = blockIdx.x / (16 * HEADS);
    const int bh = b * HEADS + h;
    const int q0 = qt * 128;
    const int r0 = 16 * w + g;

    // ---- Q fragments straight from global into registers (one time) ----
    uint32_t qa[4][4];
    {
        const uint32_t* Qr0 = Qt + ((size_t)bh * NN + q0 + r0) * (HD / 2);
        const uint32_t* Qr8 = Qr0 + 8 * (HD / 2);
#pragma unroll
        for (int kb = 0; kb < 4; kb++) {
            uint2 lo = *(const uint2*)&Qr0[kb * 8 + 2 * t];
            uint2 hi = *(const uint2*)&Qr8[kb * 8 + 2 * t];
            qa[kb][0] = lo.x; qa[kb][1] = hi.x; qa[kb][2] = lo.y; qa[kb][3] = hi.y;
        }
    }

    float o[8][4];
#pragma unroll
    for (int nt = 0; nt < 8; nt++)
#pragma unroll
        for (int r = 0; r < 4; r++) o[nt][r] = 0.0f;
    float m0 = -CUDART_INF_F, m1 = -CUDART_INF_F, l0 = 0.0f, l1 = 0.0f;

    const uint32_t* Kbase = Kt + (size_t)bh * NN * (HD / 2);
    const uint32_t* Vbase = Vt + (size_t)bh * HD * (NN / 2);

    const int ld_row = tid >> 3, ld_c = (tid & 7) * 4;
    const int ld_row2 = 32 + ld_row;

    uint4 kf[2], vf[2];
#define ATT_LDG(kt) do {                                                      \
    kf[0] = *(const uint4*)&Kbase[((size_t)(kt) * 64 + ld_row)  * (HD / 2) + ld_c]; \
    kf[1] = *(const uint4*)&Kbase[((size_t)(kt) * 64 + ld_row2) * (HD / 2) + ld_c]; \
    vf[0] = *(const uint4*)&Vbase[(size_t)ld_row  * (NN / 2) + (kt) * 32 + ld_c];   \
    vf[1] = *(const uint4*)&Vbase[(size_t)ld_row2 * (NN / 2) + (kt) * 32 + ld_c];   \
    } while (0)

    ATT_LDG(0);

    for (int kt = 0; kt < NN / 64; kt++) {
        const int base = (kt & 1) * 5120;           // [Ks 2560 | Vs 2560]
        *(uint4*)&dsm[base + ld_row  * AST + ld_c]        = kf[0];
        *(uint4*)&dsm[base + ld_row2 * AST + ld_c]        = kf[1];
        *(uint4*)&dsm[base + 2560 + ld_row  * AST + ld_c] = vf[0];
        *(uint4*)&dsm[base + 2560 + ld_row2 * AST + ld_c] = vf[1];
        __syncthreads();
        if (kt + 1 < NN / 64) ATT_LDG(kt + 1);   // overlaps compute below

        // ---- S = Q @ K^T : 4 k16 blocks over d=64, Q from registers ----
        float s[8][4];
#pragma unroll
        for (int nt = 0; nt < 8; nt++)
#pragma unroll
            for (int r = 0; r < 4; r++) s[nt][r] = 0.0f;

#pragma unroll
        for (int kb = 0; kb < 4; kb++) {
#pragma unroll
            for (int nt = 0; nt < 8; nt++) {
                uint2 bb = *(const uint2*)&dsm[base + (nt * 8 + g) * AST + kb * 8 + 2 * t];
                uint32_t bf2[2] = {bb.x, bb.y};
                mma_f16(s[nt], qa[kb], bf2);
            }
        }

        // ---- online softmax (rows g and g+8; quad-local) ----
        float mx0 = -CUDART_INF_F, mx1 = -CUDART_INF_F;
#pragma unroll
        for (int nt = 0; nt < 8; nt++) {
            mx0 = fmaxf(mx0, fmaxf(s[nt][0], s[nt][1]));
            mx1 = fmaxf(mx1, fmaxf(s[nt][2], s[nt][3]));
        }
        mx0 = fmaxf(mx0, __shfl_xor_sync(0xffffffffu, mx0, 1));
        mx0 = fmaxf(mx0, __shfl_xor_sync(0xffffffffu, mx0, 2));
        mx1 = fmaxf(mx1, __shfl_xor_sync(0xffffffffu, mx1, 1));
        mx1 = fmaxf(mx1, __shfl_xor_sync(0xffffffffu, mx1, 2));
        const float nm0 = fmaxf(m0, mx0), nm1 = fmaxf(m1, mx1);
        const float cr0 = __expf(m0 - nm0), cr1 = __expf(m1 - nm1);
        float rs0 = 0.0f, rs1 = 0.0f;
#pragma unroll
        for (int nt = 0; nt < 8; nt++) {
            s[nt][0] = __expf(s[nt][0] - nm0);
            s[nt][1] = __expf(s[nt][1] - nm0);
            s[nt][2] = __expf(s[nt][2] - nm1);
            s[nt][3] = __expf(s[nt][3] - nm1);
            rs0 += s[nt][0] + s[nt][1];
            rs1 += s[nt][2] + s[nt][3];
        }
        rs0 += __shfl_xor_sync(0xffffffffu, rs0, 1);
        rs0 += __shfl_xor_sync(0xffffffffu, rs0, 2);
        rs1 += __shfl_xor_sync(0xffffffffu, rs1, 1);
        rs1 += __shfl_xor_sync(0xffffffffu, rs1, 2);
        l0 = l0 * cr0 + rs0;  m0 = nm0;
        l1 = l1 * cr1 + rs1;  m1 = nm1;
#pragma unroll
        for (int nt = 0; nt < 8; nt++) {
            o[nt][0] *= cr0; o[nt][1] *= cr0;
            o[nt][2] *= cr1; o[nt][3] *= cr1;
        }

        // ---- O += P @ V : P fragments packed from registers (no smem) ----
#pragma unroll
        for (int kb = 0; kb < 4; kb++) {
            uint32_t a[4];
            a[0] = packh2(s[2 * kb][0],     s[2 * kb][1]);      // row g,   keys 16kb+2t,+1
            a[1] = packh2(s[2 * kb][2],     s[2 * kb][3]);      // row g+8, keys 16kb+2t,+1
            a[2] = packh2(s[2 * kb + 1][0], s[2 * kb + 1][1]);  // row g,   keys 16kb+8+2t,+1
            a[3] = packh2(s[2 * kb + 1][2], s[2 * kb + 1][3]);  // row g+8
#pragma unroll
            for (int nt = 0; nt < 8; nt++) {
                uint2 bb = *(const uint2*)&dsm[base + 2560 + (nt * 8 + g) * AST + kb * 8 + 2 * t];
                uint32_t bf2[2] = {bb.x, bb.y};
                mma_f16(o[nt], a, bf2);
            }
        }
    }

    // ---- epilogue: normalize, write packed fp16 in GEMM-A layout ----
    const float inv0 = 1.0f / l0, inv1 = 1.0f / l1;
    const int grow = b * NN + q0 + 16 * w + g;
    uint32_t* ar0 = att16 + (size_t)grow * (DIMC / 2);
    uint32_t* ar1 = att16 + (size_t)(grow + 8) * (DIMC / 2);
#pragma unroll
    for (int nt = 0; nt < 8; nt++) {
        const int wd = h * 32 + 4 * nt + t;            // global word index
        const int pos = (wd & ~7) + p8(wd & 7);
        ar0[pos] = packh2(o[nt][0] * inv0, o[nt][1] * inv0);
        ar1[pos] = packh2(o[nt][2] * inv1, o[nt][3] * inv1);
    }
#undef ATT_LDG
}

// ---------------------------------------------------------------------------
extern "C" void kernel_launch(void* const* d_in, const int* in_sizes, int n_in,
                              void* d_out, int out_size)
{
    const float* x      = (const float*)d_in[0];
    const float* w_qkv  = (const float*)d_in[1];
    const float* b_qkv  = (const float*)d_in[2];
    const float* w_proj = (const float*)d_in[3];
    const float* b_proj = (const float*)d_in[4];
    float* out = (float*)d_out;

    float *qkv_s = nullptr;
    uint32_t *x16_s = nullptr, *att16_s = nullptr;
    uint32_t *wt_s = nullptr, *qt_s = nullptr, *kt_s = nullptr, *vt_s = nullptr;
    cudaGetSymbolAddress((void**)&qkv_s,  g_qkv);
    cudaGetSymbolAddress((void**)&x16_s,  g_x16);
    cudaGetSymbolAddress((void**)&att16_s, g_att16);
    cudaGetSymbolAddress((void**)&wt_s,   g_wt);
    cudaGetSymbolAddress((void**)&qt_s,   g_qt);
    cudaGetSymbolAddress((void**)&kt_s,   g_kt);
    cudaGetSymbolAddress((void**)&vt_s,   g_vt);

    cudaFuncSetAttribute(gemm_mma, cudaFuncAttributeMaxDynamicSharedMemorySize, GEMM_SMEM);
    cudaFuncSetAttribute(attn_mma, cudaFuncAttributeMaxDynamicSharedMemorySize, ATT_SMEM);

    uint32_t* wqkvT = wt_s;
    uint32_t* wprjT = wt_s + (size_t)(3 * DIMC) * (DIMC / 2);

    // 0) weight transposes + x packing (fp16, word-permuted)
    transpose_w<<<dim3((3 * DIMC) / 32, DIMC / 32), dim3(16, 16)>>>(w_qkv, wqkvT, 3 * DIMC);
    transpose_w<<<dim3(DIMC / 32, DIMC / 32), dim3(16, 16)>>>(w_proj, wprjT, DIMC);
    prep_x<<<(MTOK * (DIMC / 2)) / 1024, 256>>>(x, x16_s);

    // 1) QKV GEMM with fused Q/K packing (V written fp32 to g_qkv)
    gemm_mma<<<dim3((3 * DIMC) / 128, MTOK / 128), 256, GEMM_SMEM>>>(
        x16_s, wqkvT, b_qkv, qkv_s, qt_s, kt_s, 3 * DIMC, DIMC, 1);

    // 2) prepass: V transposed fp16 packed
    prep_v<<<dim3(NN / 32, HD / 32, BB * HEADS), dim3(16, 16)>>>(qkv_s, vt_s);

    // 3) flash attention (output packed fp16 in GEMM-A layout)
    attn_mma<<<BB * HEADS * 16, 256, ATT_SMEM>>>(qt_s, kt_s, vt_s, att16_s);

    // 4) projection GEMM: [8192,768] @ [768,768] + bias (fp32 out)
    gemm_mma<<<dim3(DIMC / 128, MTOK / 128), 256, GEMM_SMEM>>>(
        att16_s, wprjT, b_proj, out, nullptr, nullptr, DIMC, DIMC, 0);
}